// round 5
// baseline (speedup 1.0000x reference)
#include <cuda_runtime.h>
#include <cuda_bf16.h>
#include <math.h>

#define HDIM 64
#define KDIM 256
#define HW   65536
#define NPTS 262144
#define RATE_F 0.999f
#define EPS_F  1e-6f

typedef unsigned long long u64;

// Persistent device scratch (allocation-free rule).
__device__ __align__(16) float g_m  [KDIM * HDIM];
__device__ __align__(16) float g_mn [KDIM * HDIM];
__device__ __align__(16) float g_sum[KDIM * HDIM];
__device__ float g_cnt[KDIM];
__device__ float g_nrm[KDIM];

// ---- packed f32x2 helpers (FFMA2: 2 MACs / issue slot on sm_103a) ----
__device__ __forceinline__ u64 pack2(float lo, float hi) {
    u64 r; asm("mov.b64 %0, {%1, %2};" : "=l"(r) : "f"(lo), "f"(hi)); return r;
}
__device__ __forceinline__ void unpack2(u64 v, float& lo, float& hi) {
    asm("mov.b64 {%0, %1}, %2;" : "=f"(lo), "=f"(hi) : "l"(v));
}
__device__ __forceinline__ void fma2(u64& d, u64 a, u64 b) {
    asm("fma.rn.f32x2 %0, %1, %2, %0;" : "+l"(d) : "l"(a), "l"(b));
}

// ---------------------------------------------------------------------------
// prep: m = units; mn = normalize(m); nrm = |m|; zero sums/counts.
// ---------------------------------------------------------------------------
__global__ void prep_kernel(const float* __restrict__ units) {
    int warp = threadIdx.x >> 5, lane = threadIdx.x & 31;
    int k = blockIdx.x * 8 + warp;
    if (k >= KDIM) return;
    float v0 = units[k * HDIM + lane];
    float v1 = units[k * HDIM + 32 + lane];
    g_m[k * HDIM + lane]      = v0;
    g_m[k * HDIM + 32 + lane] = v1;
    float ssq = v0 * v0 + v1 * v1;
    #pragma unroll
    for (int o = 16; o; o >>= 1) ssq += __shfl_xor_sync(0xFFFFFFFFu, ssq, o);
    float nrm = sqrtf(ssq);
    float inv = 1.0f / fmaxf(nrm, 1e-12f);
    g_mn[k * HDIM + lane]      = v0 * inv;
    g_mn[k * HDIM + 32 + lane] = v1 * inv;
    g_sum[k * HDIM + lane]      = 0.0f;
    g_sum[k * HDIM + 32 + lane] = 0.0f;
    if (lane == 0) { g_cnt[k] = 0.0f; g_nrm[k] = nrm; }
}

// ---------------------------------------------------------------------------
// assign: 1 point/thread (FFMA2), argmax over k of (xf . mn_k), scatter sums.
// launch_bounds(256,2): <=128 regs -> 2 CTAs/SM (smem 2x64KB) -> 16 warps/SM.
// grid = NPTS/256. dyn smem = 64 KB (mn).
// ---------------------------------------------------------------------------
__global__ void __launch_bounds__(256, 2) assign_kernel(const float* __restrict__ x) {
    extern __shared__ ulonglong2 smq[];          // 4096 x 16B = mn tile
    const ulonglong2* gm = (const ulonglong2*)g_mn;
    #pragma unroll 4
    for (int i = threadIdx.x; i < KDIM * HDIM / 4; i += 256) smq[i] = gm[i];
    __syncthreads();

    int p = blockIdx.x * 256 + threadIdx.x;
    int b = p >> 16;
    const float* xp = x + (size_t)b * HDIM * HW + (p & (HW - 1));

    u64 xr[HDIM / 2];
    #pragma unroll
    for (int i = 0; i < HDIM / 2; i++)
        xr[i] = pack2(xp[(size_t)(2 * i) * HW], xp[(size_t)(2 * i + 1) * HW]);

    float best = -1e30f;
    int   bi   = 0;
    for (int k = 0; k < KDIM; k++) {
        u64 d0 = 0ull, d1 = 0ull;
        const ulonglong2* row = smq + k * 16;
        #pragma unroll
        for (int i = 0; i < 16; i++) {
            ulonglong2 q = row[i];
            fma2(d0, xr[2 * i],     q.x);
            fma2(d1, xr[2 * i + 1], q.y);
        }
        float e0, e1, e2, e3;
        unpack2(d0, e0, e1); unpack2(d1, e2, e3);
        float d = (e0 + e1) + (e2 + e3);
        if (d > best) { best = d; bi = k; }
    }

    float* dst = g_sum + bi * HDIM;
    #pragma unroll
    for (int i = 0; i < 16; i++) {
        float f0, f1, f2, f3;
        unpack2(xr[2 * i], f0, f1); unpack2(xr[2 * i + 1], f2, f3);
        asm volatile("red.global.add.v4.f32 [%0], {%1,%2,%3,%4};"
                     :: "l"(dst + 4 * i), "f"(f0), "f"(f1), "f"(f2), "f"(f3) : "memory");
    }
    atomicAdd(g_cnt + bi, 1.0f);
}

// ---------------------------------------------------------------------------
// update: m = m*RATE + (sum/(cnt+eps))*(1-RATE); refresh mn, nrm; zero sums.
// ---------------------------------------------------------------------------
__global__ void update_kernel() {
    int warp = threadIdx.x >> 5, lane = threadIdx.x & 31;
    int k = blockIdx.x * 8 + warp;
    if (k >= KDIM) return;
    const float IR = 1.0f - RATE_F;
    float sc = IR / (g_cnt[k] + EPS_F);
    float m0 = g_m[k * HDIM + lane]      * RATE_F + g_sum[k * HDIM + lane]      * sc;
    float m1 = g_m[k * HDIM + 32 + lane] * RATE_F + g_sum[k * HDIM + 32 + lane] * sc;
    g_m[k * HDIM + lane]      = m0;
    g_m[k * HDIM + 32 + lane] = m1;
    float ssq = m0 * m0 + m1 * m1;
    #pragma unroll
    for (int o = 16; o; o >>= 1) ssq += __shfl_xor_sync(0xFFFFFFFFu, ssq, o);
    float nrm = sqrtf(ssq);
    float inv = 1.0f / fmaxf(nrm, 1e-12f);
    g_mn[k * HDIM + lane]      = m0 * inv;
    g_mn[k * HDIM + 32 + lane] = m1 * inv;
    g_sum[k * HDIM + lane]      = 0.0f;
    g_sum[k * HDIM + 32 + lane] = 0.0f;
    if (lane == 0) { g_cnt[k] = 0.0f; g_nrm[k] = nrm; }
}

// ---------------------------------------------------------------------------
// out: 2 threads per point (32 dims each) to halve per-thread registers and
// double occupancy. Full dot via shfl_xor(.,1); both threads compute identical
// exp/den (deterministic). Single softmax pass (score in [-1,1] => exp safe).
// m_k reconstructed as mn_k * nrm_k so one mn row read serves dot AND acc.
// launch_bounds(256,2). grid = 2*NPTS/256. dyn smem = 65 KB.
// ---------------------------------------------------------------------------
__global__ void __launch_bounds__(256, 2) out_kernel(const float* __restrict__ x,
                                                     float* __restrict__ out) {
    extern __shared__ ulonglong2 smem_raw[];
    ulonglong2* smq = smem_raw;                                  // mn: 4096 x 16B
    float* snrm = (float*)(smem_raw + KDIM * HDIM / 4);          // nrm: 256 floats
    const ulonglong2* gm = (const ulonglong2*)g_mn;
    #pragma unroll 4
    for (int i = threadIdx.x; i < KDIM * HDIM / 4; i += 256) smq[i] = gm[i];
    if (threadIdx.x < KDIM) snrm[threadIdx.x] = g_nrm[threadIdx.x];
    __syncthreads();

    int t = blockIdx.x * 256 + threadIdx.x;
    int p = t >> 1;                 // point id
    int h = t & 1;                  // which half of the 64 dims
    int b = p >> 16;
    const float* xp = x + (size_t)b * HDIM * HW + (p & (HW - 1)) + (size_t)(h * 32) * HW;

    u64 xr[16];
    float ss = 0.0f;
    #pragma unroll
    for (int i = 0; i < 16; i++) {
        float f0 = xp[(size_t)(2 * i) * HW];
        float f1 = xp[(size_t)(2 * i + 1) * HW];
        xr[i] = pack2(f0, f1);
        ss = fmaf(f0, f0, fmaf(f1, f1, ss));
    }
    ss += __shfl_xor_sync(0xFFFFFFFFu, ss, 1);
    float invn = 1.0f / fmaxf(sqrtf(ss), 1e-12f);

    u64 acc[16];
    #pragma unroll
    for (int i = 0; i < 16; i++) acc[i] = 0ull;
    float den = 0.0f;

    for (int k = 0; k < KDIM; k++) {
        const ulonglong2* row = smq + k * 16 + h * 8;   // my 32-dim half of mn_k
        u64 v[16];
        #pragma unroll
        for (int i = 0; i < 8; i++) { ulonglong2 q = row[i]; v[2 * i] = q.x; v[2 * i + 1] = q.y; }

        u64 d0 = 0ull, d1 = 0ull;
        #pragma unroll
        for (int i = 0; i < 8; i++) {
            fma2(d0, xr[2 * i],     v[2 * i]);
            fma2(d1, xr[2 * i + 1], v[2 * i + 1]);
        }
        float e0, e1, e2, e3;
        unpack2(d0, e0, e1); unpack2(d1, e2, e3);
        float dh = (e0 + e1) + (e2 + e3);
        float d  = dh + __shfl_xor_sync(0xFFFFFFFFu, dh, 1);
        float e  = __expf(d * invn);
        den += e;
        float w = e * snrm[k];
        u64 w2 = pack2(w, w);
        #pragma unroll
        for (int i = 0; i < 16; i++) fma2(acc[i], w2, v[i]);
    }

    float iden = 1.0f / den;
    float* ob = out + (size_t)b * HDIM * HW + (p & (HW - 1)) + (size_t)(h * 32) * HW;
    #pragma unroll
    for (int i = 0; i < 16; i++) {
        float f0, f1;
        unpack2(acc[i], f0, f1);
        ob[(size_t)(2 * i) * HW]     = f0 * iden;
        ob[(size_t)(2 * i + 1) * HW] = f1 * iden;
    }
}

// ---------------------------------------------------------------------------
extern "C" void kernel_launch(void* const* d_in, const int* in_sizes, int n_in,
                              void* d_out, int out_size) {
    const float* x;
    const float* units;
    if (in_sizes[0] >= in_sizes[1]) { x = (const float*)d_in[0]; units = (const float*)d_in[1]; }
    else                            { x = (const float*)d_in[1]; units = (const float*)d_in[0]; }
    float* out = (float*)d_out;

    const int mn_bytes  = KDIM * HDIM * (int)sizeof(float);      // 64 KB
    const int out_bytes = mn_bytes + KDIM * (int)sizeof(float);  // 65 KB
    cudaFuncSetAttribute(assign_kernel, cudaFuncAttributeMaxDynamicSharedMemorySize, mn_bytes);
    cudaFuncSetAttribute(out_kernel,    cudaFuncAttributeMaxDynamicSharedMemorySize, out_bytes);

    prep_kernel<<<32, 256>>>(units);
    for (int it = 0; it < 3; it++) {
        assign_kernel<<<NPTS / 256, 256, mn_bytes>>>(x);
        update_kernel<<<32, 256>>>();
    }
    out_kernel<<<2 * NPTS / 256, 256, out_bytes>>>(x, out);
}

// round 6
// speedup vs baseline: 1.2123x; 1.2123x over previous
#include <cuda_runtime.h>
#include <cuda_bf16.h>
#include <math.h>

#define HDIM 64
#define KDIM 256
#define HW   65536
#define NPTS 262144
#define RATE_F 0.999f
#define EPS_F  1e-6f
#define XPAD 68            // padded x-tile row (floats); 272B, 16B-aligned

typedef unsigned long long u64;

// Persistent device scratch (allocation-free rule).
__device__ __align__(16) float g_m  [KDIM * HDIM];   // codebook [k][c]
__device__ __align__(16) float g_mn [KDIM * HDIM];   // normalized [k][c] (for out)
__device__ __align__(16) float g_mnT[HDIM * KDIM];   // normalized transposed [c][k] (for assign)
__device__ __align__(16) float g_sum[KDIM * HDIM];
__device__ float g_cnt[KDIM];
__device__ float g_nrm[KDIM];

// ---- packed f32x2 helpers (FFMA2: 2 MACs / issue slot on sm_103a) ----
__device__ __forceinline__ u64 pack2(float lo, float hi) {
    u64 r; asm("mov.b64 %0, {%1, %2};" : "=l"(r) : "f"(lo), "f"(hi)); return r;
}
__device__ __forceinline__ void unpack2(u64 v, float& lo, float& hi) {
    asm("mov.b64 {%0, %1}, %2;" : "=f"(lo), "=f"(hi) : "l"(v));
}
__device__ __forceinline__ void fma2(u64& d, u64 a, u64 b) {
    asm("fma.rn.f32x2 %0, %1, %2, %0;" : "+l"(d) : "l"(a), "l"(b));
}

// ---------------------------------------------------------------------------
// prep: m = units; mn = normalize(m); mnT transposed copy; nrm; zero sums.
// ---------------------------------------------------------------------------
__global__ void prep_kernel(const float* __restrict__ units) {
    int warp = threadIdx.x >> 5, lane = threadIdx.x & 31;
    int k = blockIdx.x * 8 + warp;
    if (k >= KDIM) return;
    float v0 = units[k * HDIM + lane];
    float v1 = units[k * HDIM + 32 + lane];
    g_m[k * HDIM + lane]      = v0;
    g_m[k * HDIM + 32 + lane] = v1;
    float ssq = v0 * v0 + v1 * v1;
    #pragma unroll
    for (int o = 16; o; o >>= 1) ssq += __shfl_xor_sync(0xFFFFFFFFu, ssq, o);
    float nrm = sqrtf(ssq);
    float inv = 1.0f / fmaxf(nrm, 1e-12f);
    g_mn[k * HDIM + lane]      = v0 * inv;
    g_mn[k * HDIM + 32 + lane] = v1 * inv;
    g_mnT[lane * KDIM + k]        = v0 * inv;
    g_mnT[(32 + lane) * KDIM + k] = v1 * inv;
    g_sum[k * HDIM + lane]      = 0.0f;
    g_sum[k * HDIM + 32 + lane] = 0.0f;
    if (lane == 0) { g_cnt[k] = 0.0f; g_nrm[k] = nrm; }
}

// ---------------------------------------------------------------------------
// assign (register-tiled GEMM): CTA = 64 pts x 256 k. Warp owns 8 pts; lane
// owns k = lane + 32j (j<8). acc packed over point-pairs: acc[4][8] f32x2.
// Per c: 2 bcast LDS.128 (x pairs) + 8 coalesced LDS.32 (mnT) + 32 fma2.
// Then per-point argmax (lane-local + shuffle butterfly, lowest-k ties) and
// warp-cooperative scatter of x into g_sum. dyn smem = 81 KB, 2 CTAs/SM.
// ---------------------------------------------------------------------------
__global__ void __launch_bounds__(256, 2) assign_kernel(const float* __restrict__ x) {
    extern __shared__ float smem[];
    float* smnT = smem;                    // [64 c][256 k] = 64 KB
    float* sx   = smem + HDIM * KDIM;      // [64 c][XPAD]  = 17 KB

    // Load mnT (coalesced 16B copy).
    {
        const ulonglong2* gm = (const ulonglong2*)g_mnT;
        ulonglong2* sm2 = (ulonglong2*)smnT;
        #pragma unroll 4
        for (int i = threadIdx.x; i < HDIM * KDIM / 4; i += 256) sm2[i] = gm[i];
    }
    // Load x tile: 64 consecutive points (same batch: 64 | HW).
    int hw0 = blockIdx.x * 64;
    int b   = hw0 >> 16;
    int hwb = hw0 & (HW - 1);
    const float* xg = x + (size_t)b * HDIM * HW + hwb;
    #pragma unroll 4
    for (int i = threadIdx.x; i < HDIM * 64; i += 256) {
        int c = i >> 6, pt = i & 63;
        sx[c * XPAD + pt] = xg[(size_t)c * HW + pt];
    }
    __syncthreads();

    int w = threadIdx.x >> 5, lane = threadIdx.x & 31;
    int ptBase = 8 * w;

    u64 acc[4][8];
    #pragma unroll
    for (int pp = 0; pp < 4; pp++)
        #pragma unroll
        for (int j = 0; j < 8; j++) acc[pp][j] = 0ull;

    #pragma unroll 2
    for (int c = 0; c < HDIM; c++) {
        const ulonglong2* xr = (const ulonglong2*)(sx + c * XPAD + ptBase);
        ulonglong2 xq0 = xr[0];
        ulonglong2 xq1 = xr[1];
        u64 xp0 = xq0.x, xp1 = xq0.y, xp2 = xq1.x, xp3 = xq1.y;
        const float* mrow = smnT + c * KDIM + lane;
        u64 mnd[8];
        #pragma unroll
        for (int j = 0; j < 8; j++) { float v = mrow[32 * j]; mnd[j] = pack2(v, v); }
        #pragma unroll
        for (int j = 0; j < 8; j++) {
            fma2(acc[0][j], xp0, mnd[j]);
            fma2(acc[1][j], xp1, mnd[j]);
            fma2(acc[2][j], xp2, mnd[j]);
            fma2(acc[3][j], xp3, mnd[j]);
        }
    }

    // Per-point argmax over all 256 k, then scatter.
    #pragma unroll
    for (int pl = 0; pl < 8; pl++) {
        const int pp = pl >> 1, hi = pl & 1;
        float best = -1e30f; int bj = 0;
        #pragma unroll
        for (int j = 0; j < 8; j++) {
            float lo_, hi_;
            unpack2(acc[pp][j], lo_, hi_);
            float d = hi ? hi_ : lo_;
            if (d > best) { best = d; bj = j; }
        }
        int bk = lane + 32 * bj;
        #pragma unroll
        for (int o = 16; o; o >>= 1) {
            float ov = __shfl_xor_sync(0xFFFFFFFFu, best, o);
            int   ok = __shfl_xor_sync(0xFFFFFFFFu, bk,   o);
            if (ov > best || (ov == best && ok < bk)) { best = ov; bk = ok; }
        }
        // Warp-cooperative scatter of x[pt] (64 floats) into g_sum[bk].
        int pt = ptBase + pl;
        float v0 = sx[lane * XPAD + pt];
        float v1 = sx[(32 + lane) * XPAD + pt];
        atomicAdd(g_sum + bk * HDIM + lane,      v0);
        atomicAdd(g_sum + bk * HDIM + 32 + lane, v1);
        if (lane == 0) atomicAdd(g_cnt + bk, 1.0f);
    }
}

// ---------------------------------------------------------------------------
// update: m = m*RATE + (sum/(cnt+eps))*(1-RATE); refresh mn/mnT/nrm; zero sums.
// ---------------------------------------------------------------------------
__global__ void update_kernel() {
    int warp = threadIdx.x >> 5, lane = threadIdx.x & 31;
    int k = blockIdx.x * 8 + warp;
    if (k >= KDIM) return;
    const float IR = 1.0f - RATE_F;
    float sc = IR / (g_cnt[k] + EPS_F);
    float m0 = g_m[k * HDIM + lane]      * RATE_F + g_sum[k * HDIM + lane]      * sc;
    float m1 = g_m[k * HDIM + 32 + lane] * RATE_F + g_sum[k * HDIM + 32 + lane] * sc;
    g_m[k * HDIM + lane]      = m0;
    g_m[k * HDIM + 32 + lane] = m1;
    float ssq = m0 * m0 + m1 * m1;
    #pragma unroll
    for (int o = 16; o; o >>= 1) ssq += __shfl_xor_sync(0xFFFFFFFFu, ssq, o);
    float nrm = sqrtf(ssq);
    float inv = 1.0f / fmaxf(nrm, 1e-12f);
    g_mn[k * HDIM + lane]      = m0 * inv;
    g_mn[k * HDIM + 32 + lane] = m1 * inv;
    g_mnT[lane * KDIM + k]        = m0 * inv;
    g_mnT[(32 + lane) * KDIM + k] = m1 * inv;
    g_sum[k * HDIM + lane]      = 0.0f;
    g_sum[k * HDIM + 32 + lane] = 0.0f;
    if (lane == 0) { g_cnt[k] = 0.0f; g_nrm[k] = nrm; }
}

// ---------------------------------------------------------------------------
// out (R4 version): 1 pt/thread, single softmax pass (score in [-1,1] => exp
// safe without max-shift), m_k = mn_k * nrm_k so one mn row serves dot + acc.
// ---------------------------------------------------------------------------
__global__ void __launch_bounds__(256, 1) out_kernel(const float* __restrict__ x,
                                                     float* __restrict__ out) {
    extern __shared__ ulonglong2 smem_raw[];
    ulonglong2* smq = smem_raw;                                  // mn: 4096 x 16B
    float* snrm = (float*)(smem_raw + KDIM * HDIM / 4);          // nrm: 256 floats
    const ulonglong2* gm = (const ulonglong2*)g_mn;
    #pragma unroll 4
    for (int i = threadIdx.x; i < KDIM * HDIM / 4; i += 256) smq[i] = gm[i];
    if (threadIdx.x < KDIM) snrm[threadIdx.x] = g_nrm[threadIdx.x];
    __syncthreads();

    int p  = blockIdx.x * 256 + threadIdx.x;
    int b  = p >> 16;
    const float* xb = x + (size_t)b * HDIM * HW + (p & (HW - 1));

    u64 xr[HDIM / 2];
    float s0 = 0.f, s1 = 0.f;
    #pragma unroll
    for (int i = 0; i < HDIM / 2; i++) {
        float f0 = xb[(size_t)(2 * i) * HW];
        float f1 = xb[(size_t)(2 * i + 1) * HW];
        xr[i] = pack2(f0, f1);
        s0 = fmaf(f0, f0, s0);
        s1 = fmaf(f1, f1, s1);
    }
    float invn = 1.0f / fmaxf(sqrtf(s0 + s1), 1e-12f);

    u64 acc[HDIM / 2];
    #pragma unroll
    for (int i = 0; i < HDIM / 2; i++) acc[i] = 0ull;
    float den = 0.0f;

    for (int k = 0; k < KDIM; k++) {
        u64 v[HDIM / 2];
        const ulonglong2* row = smq + k * 16;
        #pragma unroll
        for (int i = 0; i < 16; i++) { ulonglong2 q = row[i]; v[2 * i] = q.x; v[2 * i + 1] = q.y; }

        u64 d0 = 0ull, d1 = 0ull;
        #pragma unroll
        for (int i = 0; i < 16; i++) {
            fma2(d0, xr[2 * i],     v[2 * i]);
            fma2(d1, xr[2 * i + 1], v[2 * i + 1]);
        }
        float e0, e1, e2, e3;
        unpack2(d0, e0, e1); unpack2(d1, e2, e3);
        float d = (e0 + e1) + (e2 + e3);
        float e = __expf(d * invn);
        den += e;
        float wv = e * snrm[k];
        u64 w2 = pack2(wv, wv);
        #pragma unroll
        for (int i = 0; i < HDIM / 2; i++) fma2(acc[i], w2, v[i]);
    }

    float iden = 1.0f / den;
    float* ob = out + (size_t)b * HDIM * HW + (p & (HW - 1));
    #pragma unroll
    for (int i = 0; i < HDIM / 2; i++) {
        float f0, f1;
        unpack2(acc[i], f0, f1);
        ob[(size_t)(2 * i) * HW]     = f0 * iden;
        ob[(size_t)(2 * i + 1) * HW] = f1 * iden;
    }
}

// ---------------------------------------------------------------------------
extern "C" void kernel_launch(void* const* d_in, const int* in_sizes, int n_in,
                              void* d_out, int out_size) {
    const float* x;
    const float* units;
    if (in_sizes[0] >= in_sizes[1]) { x = (const float*)d_in[0]; units = (const float*)d_in[1]; }
    else                            { x = (const float*)d_in[1]; units = (const float*)d_in[0]; }
    float* out = (float*)d_out;

    const int assign_bytes = (HDIM * KDIM + HDIM * XPAD) * (int)sizeof(float); // ~81 KB
    const int out_bytes    = (KDIM * HDIM + KDIM) * (int)sizeof(float);        // 65 KB
    cudaFuncSetAttribute(assign_kernel, cudaFuncAttributeMaxDynamicSharedMemorySize, assign_bytes);
    cudaFuncSetAttribute(out_kernel,    cudaFuncAttributeMaxDynamicSharedMemorySize, out_bytes);

    prep_kernel<<<32, 256>>>(units);
    for (int it = 0; it < 3; it++) {
        assign_kernel<<<NPTS / 64, 256, assign_bytes>>>(x);
        update_kernel<<<32, 256>>>();
    }
    out_kernel<<<NPTS / 256, 256, out_bytes>>>(x, out);
}